// round 1
// baseline (speedup 1.0000x reference)
#include <cuda_runtime.h>
#include <cuda_bf16.h>

// Problem constants (fixed shapes from reference)
#define NE 8        // experts
#define NC 4096     // capacity (rows per expert)
#define ND 1024     // d_model
#define NF 4096     // d_ff

// Intermediate h = relu(X @ W1): [E, C, F] fp32 scratch (device global; no allocs)
__device__ float g_h[(size_t)NE * NC * NF];   // 512 MiB

// ---------------------------------------------------------------------------
// Classic SMEM-tiled SGEMM: C[M,N] = A[M,K] (row-major) @ B[K,N] (row-major)
// BM=BN=128, BK=8, 256 threads, 8x8 per-thread microtile, float4 everywhere.
// Batched over blockIdx.z (expert) via element strides. Optional fused ReLU.
// All dims are multiples of tile sizes for this problem -> no bounds checks.
// ---------------------------------------------------------------------------
#define BM 128
#define BN 128
#define BK 8
#define TM 8
#define TN 8

template<bool RELU>
__global__ __launch_bounds__(256, 2)
void sgemm_batched(const float* __restrict__ A,
                   const float* __restrict__ B,
                   float* __restrict__ C,
                   int M, int N, int K,
                   long long strideA, long long strideB, long long strideC)
{
    const int e = blockIdx.z;
    A += (long long)e * strideA;
    B += (long long)e * strideB;
    C += (long long)e * strideC;

    __shared__ float As[BK][BM];   // transposed A tile: As[k][m]
    __shared__ float Bs[BK][BN];   // Bs[k][n]

    const int tid = threadIdx.x;

    // microtile coordinates: 16x16 thread grid, each thread does 8x8
    const int tx = tid & 15;          // col group
    const int ty = tid >> 4;          // row group

    const int block_row = blockIdx.y * BM;
    const int block_col = blockIdx.x * BN;

    // A tile load: 128 rows x 8 cols = 256 float4 (2 per row, along K)
    const int a_row = tid >> 1;            // 0..127
    const int a_col = (tid & 1) * 4;       // 0 or 4
    // B tile load: 8 rows x 128 cols = 256 float4 (32 per row, along N)
    const int b_row = tid >> 5;            // 0..7
    const int b_col = (tid & 31) * 4;      // 0..124

    const float* Aptr = A + (long long)(block_row + a_row) * K + a_col;
    const float* Bptr = B + (long long)b_row * N + block_col + b_col;

    float acc[TM][TN];
    #pragma unroll
    for (int i = 0; i < TM; i++)
        #pragma unroll
        for (int j = 0; j < TN; j++)
            acc[i][j] = 0.0f;

    for (int k0 = 0; k0 < K; k0 += BK) {
        // ---- global -> shared ----
        float4 av = *reinterpret_cast<const float4*>(Aptr + k0);
        As[a_col + 0][a_row] = av.x;
        As[a_col + 1][a_row] = av.y;
        As[a_col + 2][a_row] = av.z;
        As[a_col + 3][a_row] = av.w;

        float4 bv = *reinterpret_cast<const float4*>(Bptr + (long long)k0 * N);
        *reinterpret_cast<float4*>(&Bs[b_row][b_col]) = bv;

        __syncthreads();

        // ---- microkernel ----
        #pragma unroll
        for (int k = 0; k < BK; k++) {
            float4 ra0 = *reinterpret_cast<const float4*>(&As[k][ty * TM + 0]);
            float4 ra1 = *reinterpret_cast<const float4*>(&As[k][ty * TM + 4]);
            float4 rb0 = *reinterpret_cast<const float4*>(&Bs[k][tx * TN + 0]);
            float4 rb1 = *reinterpret_cast<const float4*>(&Bs[k][tx * TN + 4]);
            float ra[TM] = {ra0.x, ra0.y, ra0.z, ra0.w, ra1.x, ra1.y, ra1.z, ra1.w};
            float rb[TN] = {rb0.x, rb0.y, rb0.z, rb0.w, rb1.x, rb1.y, rb1.z, rb1.w};
            #pragma unroll
            for (int i = 0; i < TM; i++)
                #pragma unroll
                for (int j = 0; j < TN; j++)
                    acc[i][j] = fmaf(ra[i], rb[j], acc[i][j]);
        }

        __syncthreads();
    }

    // ---- epilogue (fused ReLU for GEMM1) ----
    float* Cptr = C + (long long)(block_row + ty * TM) * N + block_col + tx * TN;
    #pragma unroll
    for (int i = 0; i < TM; i++) {
        #pragma unroll
        for (int j = 0; j < TN; j += 4) {
            float4 v;
            v.x = acc[i][j + 0];
            v.y = acc[i][j + 1];
            v.z = acc[i][j + 2];
            v.w = acc[i][j + 3];
            if (RELU) {
                v.x = fmaxf(v.x, 0.0f);
                v.y = fmaxf(v.y, 0.0f);
                v.z = fmaxf(v.z, 0.0f);
                v.w = fmaxf(v.w, 0.0f);
            }
            *reinterpret_cast<float4*>(Cptr + (long long)i * N + j) = v;
        }
    }
}

extern "C" void kernel_launch(void* const* d_in, const int* in_sizes, int n_in,
                              void* d_out, int out_size)
{
    // metadata order: dispatched_hidden_states[E*C,D] f32,
    //                 experts_capacity_usage[E] i32 (unused by reference math),
    //                 W1[E,D,F] f32, W2[E,F,D] f32
    const float* X  = (const float*)d_in[0];
    const float* W1 = (const float*)d_in[2];
    const float* W2 = (const float*)d_in[3];
    float* Y = (float*)d_out;

    float* H = nullptr;
    cudaGetSymbolAddress((void**)&H, g_h);   // host-side lookup; no allocation, capture-safe

    dim3 blk(256, 1, 1);

    // GEMM1: h[e] = relu(X[e] @ W1[e])  -> M=C, N=F, K=D
    dim3 g1(NF / BN, NC / BM, NE);
    sgemm_batched<true><<<g1, blk>>>(X, W1, H,
                                     NC, NF, ND,
                                     (long long)NC * ND,
                                     (long long)ND * NF,
                                     (long long)NC * NF);

    // GEMM2: y[e] = h[e] @ W2[e]       -> M=C, N=D, K=F
    dim3 g2(ND / BN, NC / BM, NE);
    sgemm_batched<false><<<g2, blk>>>(H, W2, Y,
                                      NC, ND, NF,
                                      (long long)NC * NF,
                                      (long long)NF * ND,
                                      (long long)NC * ND);
}

// round 3
// speedup vs baseline: 3.1080x; 3.1080x over previous
#include <cuda_runtime.h>
#include <cstdint>
#include <cstddef>

#define NE 8
#define NC 4096
#define ND 1024
#define NF 4096

// Device scratch (no allocs allowed)
__device__ float g_Xr [(size_t)NE * NC * ND];   // X rounded to tf32
__device__ float g_W1T[(size_t)NE * NF * ND];   // W1^T [E,F,D], tf32-rounded
__device__ float g_W2T[(size_t)NE * ND * NF];   // W2^T [E,D,F], tf32-rounded
__device__ float g_H  [(size_t)NE * NC * NF];   // relu(X@W1), tf32-rounded

// ---------------- helpers ----------------
__device__ __forceinline__ uint32_t smem_u32(const void* p) {
    uint32_t a;
    asm("{ .reg .u64 t; cvta.to.shared.u64 t, %1; cvt.u32.u64 %0, t; }" : "=r"(a) : "l"(p));
    return a;
}
__device__ __forceinline__ void cp_async16(uint32_t dst, const void* src) {
    asm volatile("cp.async.cg.shared.global [%0], [%1], 16;" :: "r"(dst), "l"(src));
}
#define CP_COMMIT() asm volatile("cp.async.commit_group;" ::: "memory")
#define CP_WAIT2()  asm volatile("cp.async.wait_group 2;" ::: "memory")

__device__ __forceinline__ float rna_tf32(float v) {
    uint32_t t;
    asm("cvt.rna.tf32.f32 %0, %1;" : "=r"(t) : "f"(v));
    return __uint_as_float(t);
}

__device__ __forceinline__ void mma_tf32(float d[4],
                                         uint32_t a0, uint32_t a1, uint32_t a2, uint32_t a3,
                                         uint32_t b0, uint32_t b1) {
    asm volatile("mma.sync.aligned.m16n8k8.row.col.f32.tf32.tf32.f32 "
        "{%0,%1,%2,%3}, {%4,%5,%6,%7}, {%8,%9}, {%0,%1,%2,%3};"
        : "+f"(d[0]), "+f"(d[1]), "+f"(d[2]), "+f"(d[3])
        : "r"(a0), "r"(a1), "r"(a2), "r"(a3), "r"(b0), "r"(b1));
}

// ---------------- prep kernels ----------------
__global__ void round_tf32_kernel(const float* __restrict__ in, float* __restrict__ out, size_t n4) {
    size_t i = (size_t)blockIdx.x * blockDim.x + threadIdx.x;
    if (i >= n4) return;
    float4 v = reinterpret_cast<const float4*>(in)[i];
    v.x = rna_tf32(v.x); v.y = rna_tf32(v.y); v.z = rna_tf32(v.z); v.w = rna_tf32(v.w);
    reinterpret_cast<float4*>(out)[i] = v;
}

// out[e][c][r] = rna(in[e][r][c]); in: [R, C]
__global__ void transpose_rna_kernel(const float* __restrict__ in, float* __restrict__ out,
                                     int R, int C) {
    __shared__ float tile[32][33];
    const size_t eoff = (size_t)blockIdx.z * R * C;
    in += eoff; out += eoff;
    int c0 = blockIdx.x * 32, r0 = blockIdx.y * 32;
    #pragma unroll
    for (int i = threadIdx.y; i < 32; i += 8)
        tile[i][threadIdx.x] = in[(size_t)(r0 + i) * C + c0 + threadIdx.x];
    __syncthreads();
    #pragma unroll
    for (int i = threadIdx.y; i < 32; i += 8)
        out[(size_t)(c0 + i) * R + r0 + threadIdx.x] = rna_tf32(tile[threadIdx.x][i]);
}

// ---------------- tf32 mma.sync GEMM ----------------
// C[M,N] = A[M,K] (K-major) * B[N,K]^T (B K-major), batched over blockIdx.z.
// CTA tile 128x128, BK=32, 4-stage cp.async pipeline.
// 8 warps: warpM = wid&1 (2), warpN = wid>>1 (4); warp tile 64x32.
#define STAGES 4
#define BK 32
#define TILE_M 128
#define TILE_N 128
#define SROW 36                                   // padded row stride (floats)
#define A_STG_F (TILE_M * SROW)                   // floats per A stage (4608)
#define B_STG_F (TILE_N * SROW)
#define A_STG_B (A_STG_F * 4)                     // 18432 B
#define B_STG_B (B_STG_F * 4)
#define SM_TOTAL (STAGES * (A_STG_B + B_STG_B))   // 147456 B

template<bool RELU>
__global__ __launch_bounds__(256, 1)
void gemm_tf32_mma(const float* __restrict__ A, const float* __restrict__ B,
                   float* __restrict__ C,
                   int K, int lda, int ldb, int ldc,
                   long long sA, long long sB, long long sC)
{
    extern __shared__ float smem[];                 // [STAGES*A | STAGES*B]
    float* AsBase = smem;
    float* BsBase = smem + STAGES * A_STG_F;
    const uint32_t smem_base = smem_u32(smem);
    const uint32_t b_base_u  = smem_base + STAGES * A_STG_B;

    const int tid = threadIdx.x;
    const int wid = tid >> 5;
    const int lane = tid & 31;
    const int lq = lane >> 2;      // 0..7
    const int lr = lane & 3;       // 0..3
    const int warpM = wid & 1;     // 0..1
    const int warpN = wid >> 1;    // 0..3

    const long long e = blockIdx.z;
    const float* Ag = A + e * sA + (long long)blockIdx.y * TILE_M * lda;
    const float* Bg = B + e * sB + (long long)blockIdx.x * TILE_N * ldb;
    float* Cg = C + e * sC + (long long)blockIdx.y * TILE_M * ldc + (long long)blockIdx.x * TILE_N;

    // cp.async slots: 1024 16B-chunks per matrix per stage; 4 per thread each.
    // chunk g: row = g>>3 (0..127), seg = g&7 (16B within the 128B of row data)
    uint32_t a_dst[4]; const float* a_src[4];
    uint32_t b_dst[4]; const float* b_src[4];
    #pragma unroll
    for (int j = 0; j < 4; j++) {
        int g = tid + 256 * j, row = g >> 3, seg = g & 7;
        a_dst[j] = row * (SROW * 4) + seg * 16;
        b_dst[j] = a_dst[j];
        a_src[j] = Ag + (long long)row * lda + seg * 4;
        b_src[j] = Bg + (long long)row * ldb + seg * 4;
    }

    const int niters = K / BK;

    // prologue: stages 0..2
    #pragma unroll
    for (int s = 0; s < STAGES - 1; s++) {
        const int k0 = s * BK;
        const uint32_t ao = smem_base + s * A_STG_B;
        const uint32_t bo = b_base_u + s * B_STG_B;
        #pragma unroll
        for (int j = 0; j < 4; j++) cp_async16(ao + a_dst[j], a_src[j] + k0);
        #pragma unroll
        for (int j = 0; j < 4; j++) cp_async16(bo + b_dst[j], b_src[j] + k0);
        CP_COMMIT();
    }

    float acc[4][4][4];
    #pragma unroll
    for (int i = 0; i < 4; i++)
        #pragma unroll
        for (int j = 0; j < 4; j++)
            #pragma unroll
            for (int k = 0; k < 4; k++)
                acc[i][j][k] = 0.0f;

    // per-warp smem fragment bases
    const int a_frag_row = warpM * 64 + lq;      // + mt*16 (+8)
    const int b_frag_row = warpN * 32 + lq;      // + nt*8

    for (int it = 0; it < niters; it++) {
        CP_WAIT2();
        __syncthreads();

        const int buf = it & (STAGES - 1);
        const float* As = AsBase + buf * A_STG_F;
        const float* Bs = BsBase + buf * B_STG_F;

        #pragma unroll
        for (int kk = 0; kk < 4; kk++) {
            const int kb = kk * 8 + lr;
            uint32_t af[4][4];
            #pragma unroll
            for (int mt = 0; mt < 4; mt++) {
                const float* p = As + (a_frag_row + mt * 16) * SROW + kb;
                af[mt][0] = __float_as_uint(p[0]);
                af[mt][1] = __float_as_uint(p[8 * SROW]);
                af[mt][2] = __float_as_uint(p[4]);
                af[mt][3] = __float_as_uint(p[8 * SROW + 4]);
            }
            uint32_t bf[4][2];
            #pragma unroll
            for (int nt = 0; nt < 4; nt++) {
                const float* p = Bs + (b_frag_row + nt * 8) * SROW + kb;
                bf[nt][0] = __float_as_uint(p[0]);
                bf[nt][1] = __float_as_uint(p[4]);
            }
            #pragma unroll
            for (int mt = 0; mt < 4; mt++)
                #pragma unroll
                for (int nt = 0; nt < 4; nt++)
                    mma_tf32(acc[mt][nt],
                             af[mt][0], af[mt][1], af[mt][2], af[mt][3],
                             bf[nt][0], bf[nt][1]);
        }

        __syncthreads();

        // prefetch stage it+3
        const int s = it + STAGES - 1;
        if (s < niters) {
            const int lb = s & (STAGES - 1);
            const int k0 = s * BK;
            const uint32_t ao = smem_base + lb * A_STG_B;
            const uint32_t bo = b_base_u + lb * B_STG_B;
            #pragma unroll
            for (int j = 0; j < 4; j++) cp_async16(ao + a_dst[j], a_src[j] + k0);
            #pragma unroll
            for (int j = 0; j < 4; j++) cp_async16(bo + b_dst[j], b_src[j] + k0);
        }
        CP_COMMIT();
    }

    // epilogue: accum layout c0,c1 = (row, 2*lr+{0,1}); c2,c3 = row+8
    #pragma unroll
    for (int mt = 0; mt < 4; mt++) {
        const int r0 = warpM * 64 + mt * 16 + lq;
        #pragma unroll
        for (int nt = 0; nt < 4; nt++) {
            const int c0 = warpN * 32 + nt * 8 + 2 * lr;
            float2 v0, v1;
            v0.x = acc[mt][nt][0]; v0.y = acc[mt][nt][1];
            v1.x = acc[mt][nt][2]; v1.y = acc[mt][nt][3];
            if (RELU) {
                v0.x = rna_tf32(fmaxf(v0.x, 0.0f));
                v0.y = rna_tf32(fmaxf(v0.y, 0.0f));
                v1.x = rna_tf32(fmaxf(v1.x, 0.0f));
                v1.y = rna_tf32(fmaxf(v1.y, 0.0f));
            }
            *reinterpret_cast<float2*>(Cg + (long long)r0 * ldc + c0)       = v0;
            *reinterpret_cast<float2*>(Cg + (long long)(r0 + 8) * ldc + c0) = v1;
        }
    }
}

// ---------------- launch ----------------
extern "C" void kernel_launch(void* const* d_in, const int* in_sizes, int n_in,
                              void* d_out, int out_size)
{
    const float* X  = (const float*)d_in[0];
    const float* W1 = (const float*)d_in[2];
    const float* W2 = (const float*)d_in[3];
    float* Y = (float*)d_out;

    float *Xr, *W1T, *W2T, *H;
    cudaGetSymbolAddress((void**)&Xr,  g_Xr);
    cudaGetSymbolAddress((void**)&W1T, g_W1T);
    cudaGetSymbolAddress((void**)&W2T, g_W2T);
    cudaGetSymbolAddress((void**)&H,   g_H);

    static bool attr_set = false;
    if (!attr_set) {
        cudaFuncSetAttribute(gemm_tf32_mma<true>,  cudaFuncAttributeMaxDynamicSharedMemorySize, SM_TOTAL);
        cudaFuncSetAttribute(gemm_tf32_mma<false>, cudaFuncAttributeMaxDynamicSharedMemorySize, SM_TOTAL);
        attr_set = true;
    }

    // 1) round X to tf32
    {
        size_t n4 = (size_t)NE * NC * ND / 4;
        round_tf32_kernel<<<(unsigned)((n4 + 255) / 256), 256>>>(X, Xr, n4);
    }
    // 2) W1 [E,D,F] -> W1T [E,F,D] (rounded)
    {
        dim3 g(NF / 32, ND / 32, NE), b(32, 8);
        transpose_rna_kernel<<<g, b>>>(W1, W1T, ND, NF);
    }
    // 3) W2 [E,F,D] -> W2T [E,D,F] (rounded)
    {
        dim3 g(ND / 32, NF / 32, NE), b(32, 8);
        transpose_rna_kernel<<<g, b>>>(W2, W2T, NF, ND);
    }
    // 4) GEMM1: H = relu(Xr @ W1); M=C, N=F, K=D
    {
        dim3 g(NF / TILE_N, NC / TILE_M, NE);
        gemm_tf32_mma<true><<<g, 256, SM_TOTAL>>>(
            Xr, W1T, H,
            ND, ND, ND, NF,
            (long long)NC * ND, (long long)NF * ND, (long long)NC * NF);
    }
    // 5) GEMM2: Y = H @ W2; M=C, N=D, K=F
    {
        dim3 g(ND / TILE_N, NC / TILE_M, NE);
        gemm_tf32_mma<false><<<g, 256, SM_TOTAL>>>(
            H, W2T, Y,
            NF, NF, NF, ND,
            (long long)NC * NF, (long long)ND * NF, (long long)NC * ND);
    }
}

// round 4
// speedup vs baseline: 3.5220x; 1.1332x over previous
#include <cuda_runtime.h>
#include <cstdint>
#include <cstddef>

#define NE 8
#define NC 4096
#define ND 1024
#define NF 4096

// Device scratch (no allocs allowed)
__device__ float g_Xr [(size_t)NE * NC * ND];   // X rounded to tf32
__device__ float g_W1T[(size_t)NE * NF * ND];   // W1^T [E,F,D], tf32-rounded
__device__ float g_W2T[(size_t)NE * ND * NF];   // W2^T [E,D,F], tf32-rounded
__device__ float g_H  [(size_t)NE * NC * NF];   // relu(X@W1), tf32-rounded

// ---------------- helpers ----------------
__device__ __forceinline__ uint32_t smem_u32(const void* p) {
    uint32_t a;
    asm("{ .reg .u64 t; cvta.to.shared.u64 t, %1; cvt.u32.u64 %0, t; }" : "=r"(a) : "l"(p));
    return a;
}
__device__ __forceinline__ void cp_async16(uint32_t dst, const void* src) {
    asm volatile("cp.async.cg.shared.global [%0], [%1], 16;" :: "r"(dst), "l"(src));
}
#define CP_COMMIT() asm volatile("cp.async.commit_group;" ::: "memory")
#define CP_WAIT1()  asm volatile("cp.async.wait_group 1;" ::: "memory")

__device__ __forceinline__ float rna_tf32(float v) {
    uint32_t t;
    asm("cvt.rna.tf32.f32 %0, %1;" : "=r"(t) : "f"(v));
    return __uint_as_float(t);
}

__device__ __forceinline__ void mma_tf32(float d[4],
                                         uint32_t a0, uint32_t a1, uint32_t a2, uint32_t a3,
                                         uint32_t b0, uint32_t b1) {
    asm volatile("mma.sync.aligned.m16n8k8.row.col.f32.tf32.tf32.f32 "
        "{%0,%1,%2,%3}, {%4,%5,%6,%7}, {%8,%9}, {%0,%1,%2,%3};"
        : "+f"(d[0]), "+f"(d[1]), "+f"(d[2]), "+f"(d[3])
        : "r"(a0), "r"(a1), "r"(a2), "r"(a3), "r"(b0), "r"(b1));
}

// ---------------- prep kernels ----------------
__global__ void round_tf32_kernel(const float* __restrict__ in, float* __restrict__ out, size_t n4) {
    size_t i = (size_t)blockIdx.x * blockDim.x + threadIdx.x;
    if (i >= n4) return;
    float4 v = reinterpret_cast<const float4*>(in)[i];
    v.x = rna_tf32(v.x); v.y = rna_tf32(v.y); v.z = rna_tf32(v.z); v.w = rna_tf32(v.w);
    reinterpret_cast<float4*>(out)[i] = v;
}

// out[e][c][r] = rna(in[e][r][c]); in: [R, C]
__global__ void transpose_rna_kernel(const float* __restrict__ in, float* __restrict__ out,
                                     int R, int C) {
    __shared__ float tile[32][33];
    const size_t eoff = (size_t)blockIdx.z * R * C;
    in += eoff; out += eoff;
    int c0 = blockIdx.x * 32, r0 = blockIdx.y * 32;
    #pragma unroll
    for (int i = threadIdx.y; i < 32; i += 8)
        tile[i][threadIdx.x] = in[(size_t)(r0 + i) * C + c0 + threadIdx.x];
    __syncthreads();
    #pragma unroll
    for (int i = threadIdx.y; i < 32; i += 8)
        out[(size_t)(c0 + i) * R + r0 + threadIdx.x] = rna_tf32(tile[threadIdx.x][i]);
}

// ---------------- tf32 mma.sync GEMM ----------------
// C[M,N] = A[M,K] (K-major) * B[N,K]^T (B K-major), batched over blockIdx.z.
// CTA tile 128x128, BK=32, 3-stage cp.async pipeline, 2 CTAs/SM.
// 8 warps: warpM = wid&1 (2), warpN = wid>>1 (4); warp tile 64x32.
#define STAGES 3
#define BK 32
#define TILE_M 128
#define TILE_N 128
#define SROW 36                                   // padded row stride (floats)
#define A_STG_F (TILE_M * SROW)                   // floats per A stage (4608)
#define B_STG_F (TILE_N * SROW)
#define A_STG_B (A_STG_F * 4)                     // 18432 B
#define B_STG_B (B_STG_F * 4)
#define SM_TOTAL (STAGES * (A_STG_B + B_STG_B))   // 110592 B -> 2 CTAs/SM

template<bool RELU>
__global__ __launch_bounds__(256, 2)
void gemm_tf32_mma(const float* __restrict__ A, const float* __restrict__ B,
                   float* __restrict__ C,
                   int K, int lda, int ldb, int ldc,
                   long long sA, long long sB, long long sC)
{
    extern __shared__ float smem[];                 // [STAGES*A | STAGES*B]
    float* AsBase = smem;
    float* BsBase = smem + STAGES * A_STG_F;
    const uint32_t smem_base = smem_u32(smem);
    const uint32_t b_base_u  = smem_base + STAGES * A_STG_B;

    const int tid = threadIdx.x;
    const int wid = tid >> 5;
    const int lane = tid & 31;
    const int lq = lane >> 2;      // 0..7
    const int lr = lane & 3;       // 0..3
    const int warpM = wid & 1;     // 0..1
    const int warpN = wid >> 1;    // 0..3

    const long long e = blockIdx.z;
    const float* Ag = A + e * sA + (long long)blockIdx.y * TILE_M * lda;
    const float* Bg = B + e * sB + (long long)blockIdx.x * TILE_N * ldb;
    float* Cg = C + e * sC + (long long)blockIdx.y * TILE_M * ldc + (long long)blockIdx.x * TILE_N;

    // cp.async slots: 1024 16B-chunks per matrix per stage; 4 per thread each.
    uint32_t a_dst[4]; const float* a_src[4];
    const float* b_src[4];
    #pragma unroll
    for (int j = 0; j < 4; j++) {
        int g = tid + 256 * j, row = g >> 3, seg = g & 7;
        a_dst[j] = row * (SROW * 4) + seg * 16;
        a_src[j] = Ag + (long long)row * lda + seg * 4;
        b_src[j] = Bg + (long long)row * ldb + seg * 4;
    }

    const int niters = K / BK;

    // prologue: stages 0,1
    #pragma unroll
    for (int s = 0; s < STAGES - 1; s++) {
        const int k0 = s * BK;
        const uint32_t ao = smem_base + s * A_STG_B;
        const uint32_t bo = b_base_u + s * B_STG_B;
        #pragma unroll
        for (int j = 0; j < 4; j++) cp_async16(ao + a_dst[j], a_src[j] + k0);
        #pragma unroll
        for (int j = 0; j < 4; j++) cp_async16(bo + a_dst[j], b_src[j] + k0);
        CP_COMMIT();
    }

    float acc[4][4][4];
    #pragma unroll
    for (int i = 0; i < 4; i++)
        #pragma unroll
        for (int j = 0; j < 4; j++)
            #pragma unroll
            for (int k = 0; k < 4; k++)
                acc[i][j][k] = 0.0f;

    // per-warp smem fragment bases
    const int a_frag_row = warpM * 64 + lq;      // + mt*16 (+8)
    const int b_frag_row = warpN * 32 + lq;      // + nt*8

    int buf = 0, pre = STAGES - 1;               // pre = stage index to prefetch next

    for (int it = 0; it < niters; it++) {
        CP_WAIT1();              // stage it complete; <=1 group in flight
        __syncthreads();         // all warps past reads of the buffer we're about to refill

        const float* As = AsBase + buf * A_STG_F;
        const float* Bs = BsBase + buf * B_STG_F;

        // prefetch stage it+2 into this same rotation slot family ((it+2)%3 == (it-1)%3 safe per top sync)
        if (pre < niters) {
            const int lb = pre - (pre / STAGES) * STAGES;   // pre % 3
            const int k0 = pre * BK;
            const uint32_t ao = smem_base + lb * A_STG_B;
            const uint32_t bo = b_base_u + lb * B_STG_B;
            #pragma unroll
            for (int j = 0; j < 4; j++) cp_async16(ao + a_dst[j], a_src[j] + k0);
            #pragma unroll
            for (int j = 0; j < 4; j++) cp_async16(bo + a_dst[j], b_src[j] + k0);
        }
        CP_COMMIT();
        pre++;

        #pragma unroll
        for (int kk = 0; kk < 4; kk++) {
            const int kb = kk * 8 + lr;
            uint32_t af[4][4];
            #pragma unroll
            for (int mt = 0; mt < 4; mt++) {
                const float* p = As + (a_frag_row + mt * 16) * SROW + kb;
                af[mt][0] = __float_as_uint(p[0]);
                af[mt][1] = __float_as_uint(p[8 * SROW]);
                af[mt][2] = __float_as_uint(p[4]);
                af[mt][3] = __float_as_uint(p[8 * SROW + 4]);
            }
            uint32_t bf[4][2];
            #pragma unroll
            for (int nt = 0; nt < 4; nt++) {
                const float* p = Bs + (b_frag_row + nt * 8) * SROW + kb;
                bf[nt][0] = __float_as_uint(p[0]);
                bf[nt][1] = __float_as_uint(p[4]);
            }
            #pragma unroll
            for (int mt = 0; mt < 4; mt++)
                #pragma unroll
                for (int nt = 0; nt < 4; nt++)
                    mma_tf32(acc[mt][nt],
                             af[mt][0], af[mt][1], af[mt][2], af[mt][3],
                             bf[nt][0], bf[nt][1]);
        }

        buf++;
        if (buf == STAGES) buf = 0;
    }

    // epilogue: accum layout c0,c1 = (row, 2*lr+{0,1}); c2,c3 = row+8
    #pragma unroll
    for (int mt = 0; mt < 4; mt++) {
        const int r0 = warpM * 64 + mt * 16 + lq;
        #pragma unroll
        for (int nt = 0; nt < 4; nt++) {
            const int c0 = warpN * 32 + nt * 8 + 2 * lr;
            float2 v0, v1;
            v0.x = acc[mt][nt][0]; v0.y = acc[mt][nt][1];
            v1.x = acc[mt][nt][2]; v1.y = acc[mt][nt][3];
            if (RELU) {
                v0.x = rna_tf32(fmaxf(v0.x, 0.0f));
                v0.y = rna_tf32(fmaxf(v0.y, 0.0f));
                v1.x = rna_tf32(fmaxf(v1.x, 0.0f));
                v1.y = rna_tf32(fmaxf(v1.y, 0.0f));
            }
            *reinterpret_cast<float2*>(Cg + (long long)r0 * ldc + c0)       = v0;
            *reinterpret_cast<float2*>(Cg + (long long)(r0 + 8) * ldc + c0) = v1;
        }
    }
}

// ---------------- launch ----------------
extern "C" void kernel_launch(void* const* d_in, const int* in_sizes, int n_in,
                              void* d_out, int out_size)
{
    const float* X  = (const float*)d_in[0];
    const float* W1 = (const float*)d_in[2];
    const float* W2 = (const float*)d_in[3];
    float* Y = (float*)d_out;

    float *Xr, *W1T, *W2T, *H;
    cudaGetSymbolAddress((void**)&Xr,  g_Xr);
    cudaGetSymbolAddress((void**)&W1T, g_W1T);
    cudaGetSymbolAddress((void**)&W2T, g_W2T);
    cudaGetSymbolAddress((void**)&H,   g_H);

    static bool attr_set = false;
    if (!attr_set) {
        cudaFuncSetAttribute(gemm_tf32_mma<true>,  cudaFuncAttributeMaxDynamicSharedMemorySize, SM_TOTAL);
        cudaFuncSetAttribute(gemm_tf32_mma<false>, cudaFuncAttributeMaxDynamicSharedMemorySize, SM_TOTAL);
        attr_set = true;
    }

    // 1) round X to tf32
    {
        size_t n4 = (size_t)NE * NC * ND / 4;
        round_tf32_kernel<<<(unsigned)((n4 + 255) / 256), 256>>>(X, Xr, n4);
    }
    // 2) W1 [E,D,F] -> W1T [E,F,D] (rounded)
    {
        dim3 g(NF / 32, ND / 32, NE), b(32, 8);
        transpose_rna_kernel<<<g, b>>>(W1, W1T, ND, NF);
    }
    // 3) W2 [E,F,D] -> W2T [E,D,F] (rounded)
    {
        dim3 g(ND / 32, NF / 32, NE), b(32, 8);
        transpose_rna_kernel<<<g, b>>>(W2, W2T, NF, ND);
    }
    // 4) GEMM1: H = relu(Xr @ W1); M=C, N=F, K=D
    {
        dim3 g(NF / TILE_N, NC / TILE_M, NE);
        gemm_tf32_mma<true><<<g, 256, SM_TOTAL>>>(
            Xr, W1T, H,
            ND, ND, ND, NF,
            (long long)NC * ND, (long long)NF * ND, (long long)NC * NF);
    }
    // 5) GEMM2: Y = H @ W2; M=C, N=D, K=F
    {
        dim3 g(ND / TILE_N, NC / TILE_M, NE);
        gemm_tf32_mma<false><<<g, 256, SM_TOTAL>>>(
            H, W2T, Y,
            NF, NF, NF, ND,
            (long long)NC * NF, (long long)ND * NF, (long long)NC * ND);
    }
}

// round 5
// speedup vs baseline: 6.4465x; 1.8304x over previous
#include <cuda_runtime.h>
#include <cuda_fp16.h>
#include <cstdint>
#include <cstddef>

#define NE 8
#define NC 4096
#define ND 1024
#define NF 4096

// Device scratch (no allocs allowed)
__device__ __half g_Xh  [(size_t)NE * NC * ND];   // X as fp16
__device__ __half g_W1Th[(size_t)NE * NF * ND];   // W1^T [E,F,D] fp16
__device__ __half g_W2Th[(size_t)NE * ND * NF];   // W2^T [E,D,F] fp16
__device__ __half g_Hh  [(size_t)NE * NC * NF];   // relu(X@W1) fp16

// ---------------- helpers ----------------
__device__ __forceinline__ uint32_t smem_u32(const void* p) {
    uint32_t a;
    asm("{ .reg .u64 t; cvta.to.shared.u64 t, %1; cvt.u32.u64 %0, t; }" : "=r"(a) : "l"(p));
    return a;
}
__device__ __forceinline__ void cp_async16(uint32_t dst, const void* src) {
    asm volatile("cp.async.cg.shared.global [%0], [%1], 16;" :: "r"(dst), "l"(src));
}
#define CP_COMMIT() asm volatile("cp.async.commit_group;" ::: "memory")
#define CP_WAIT2()  asm volatile("cp.async.wait_group 2;" ::: "memory")

__device__ __forceinline__ void ldmx4(uint32_t r[4], uint32_t addr) {
    asm volatile("ldmatrix.sync.aligned.m8n8.x4.shared.b16 {%0,%1,%2,%3}, [%4];"
        : "=r"(r[0]), "=r"(r[1]), "=r"(r[2]), "=r"(r[3]) : "r"(addr));
}
__device__ __forceinline__ void mma_f16(float d[4],
                                        uint32_t a0, uint32_t a1, uint32_t a2, uint32_t a3,
                                        uint32_t b0, uint32_t b1) {
    asm volatile("mma.sync.aligned.m16n8k16.row.col.f32.f16.f16.f32 "
        "{%0,%1,%2,%3}, {%4,%5,%6,%7}, {%8,%9}, {%0,%1,%2,%3};"
        : "+f"(d[0]), "+f"(d[1]), "+f"(d[2]), "+f"(d[3])
        : "r"(a0), "r"(a1), "r"(a2), "r"(a3), "r"(b0), "r"(b1));
}

// ---------------- prep kernels ----------------
__global__ void f32_to_f16_kernel(const float* __restrict__ in, __half* __restrict__ out, size_t n4) {
    size_t i = (size_t)blockIdx.x * blockDim.x + threadIdx.x;
    if (i >= n4) return;
    float4 v = reinterpret_cast<const float4*>(in)[i];
    __half2 h0 = __floats2half2_rn(v.x, v.y);
    __half2 h1 = __floats2half2_rn(v.z, v.w);
    uint2 o;
    o.x = *reinterpret_cast<uint32_t*>(&h0);
    o.y = *reinterpret_cast<uint32_t*>(&h1);
    reinterpret_cast<uint2*>(out)[i] = o;
}

// out[e][c][r] = f16(in[e][r][c]); in: [R, C] f32
__global__ void transpose_f16_kernel(const float* __restrict__ in, __half* __restrict__ out,
                                     int R, int C) {
    __shared__ float tile[32][33];
    const size_t eoff = (size_t)blockIdx.z * R * C;
    int c0 = blockIdx.x * 32, r0 = blockIdx.y * 32;
    #pragma unroll
    for (int i = threadIdx.y; i < 32; i += 8)
        tile[i][threadIdx.x] = in[eoff + (size_t)(r0 + i) * C + c0 + threadIdx.x];
    __syncthreads();
    #pragma unroll
    for (int i = threadIdx.y; i < 32; i += 8)
        out[eoff + (size_t)(c0 + i) * R + r0 + threadIdx.x] = __float2half_rn(tile[threadIdx.x][i]);
}

// ---------------- fp16 mma.sync GEMM ----------------
// C[M,N] = A[M,K] * B[N,K]^T ; A,B fp16 K-major, batched over blockIdx.z.
// CTA tile 128x128, BK=32, 4-stage cp.async pipeline, 2 CTAs/SM.
// 8 warps: warpM = wid&1, warpN = wid>>1; warp tile 64x32; mma m16n8k16.
#define STAGES 4
#define BK 32
#define TILE_M 128
#define TILE_N 128
#define ROWB 80                                   // padded bytes per smem row (64 data + 16 pad)
#define STG_B (TILE_M * ROWB)                     // 10240 B per matrix per stage
#define SM_TOTAL (STAGES * 2 * STG_B)             // 81920 B -> 2 CTAs/SM

template<bool RELU, bool OUT_HALF>
__global__ __launch_bounds__(256, 2)
void gemm_f16_mma(const __half* __restrict__ A, const __half* __restrict__ B,
                  void* __restrict__ Cv,
                  int K, int lda, int ldb, int ldc,
                  long long sA, long long sB, long long sC)
{
    extern __shared__ char smem[];
    const uint32_t a_base = smem_u32(smem);
    const uint32_t b_base = a_base + STAGES * STG_B;

    const int tid = threadIdx.x;
    const int wid = tid >> 5;
    const int lane = tid & 31;
    const int lq = lane >> 2;      // 0..7
    const int lr = lane & 3;       // 0..3
    const int warpM = wid & 1;
    const int warpN = wid >> 1;

    const long long e = blockIdx.z;
    const __half* Ag = A + e * sA + (long long)blockIdx.y * TILE_M * lda;
    const __half* Bg = B + e * sB + (long long)blockIdx.x * TILE_N * ldb;

    // cp.async: 512 16B-chunks per matrix per stage; 2 per thread each.
    // chunk g: row = g>>2 (0..127), seg = g&3 (16B = 8 halfs along k)
    uint32_t dst_off[2]; const __half* a_src[2]; const __half* b_src[2];
    #pragma unroll
    for (int j = 0; j < 2; j++) {
        int g = tid + 256 * j, row = g >> 2, seg = g & 3;
        dst_off[j] = row * ROWB + seg * 16;
        a_src[j] = Ag + (long long)row * lda + seg * 8;
        b_src[j] = Bg + (long long)row * ldb + seg * 8;
    }

    // ldmatrix lane offsets (conflict-free with ROWB=80)
    const uint32_t a_lm = (uint32_t)(warpM * 64 + (lane & 15)) * ROWB + ((lane >> 4) & 1) * 16;
    const uint32_t b_lm = (uint32_t)(warpN * 32 + (lane & 7) + ((lane >> 4) & 1) * 8) * ROWB
                          + ((lane >> 3) & 1) * 16;

    const int niters = K / BK;

    // prologue: stages 0..2
    #pragma unroll
    for (int s = 0; s < STAGES - 1; s++) {
        const int k0 = s * BK;
        const uint32_t ao = a_base + s * STG_B;
        const uint32_t bo = b_base + s * STG_B;
        #pragma unroll
        for (int j = 0; j < 2; j++) cp_async16(ao + dst_off[j], a_src[j] + k0);
        #pragma unroll
        for (int j = 0; j < 2; j++) cp_async16(bo + dst_off[j], b_src[j] + k0);
        CP_COMMIT();
    }

    float acc[4][4][4];
    #pragma unroll
    for (int i = 0; i < 4; i++)
        #pragma unroll
        for (int j = 0; j < 4; j++)
            #pragma unroll
            for (int k = 0; k < 4; k++)
                acc[i][j][k] = 0.0f;

    int pre = STAGES - 1;

    for (int it = 0; it < niters; it++) {
        CP_WAIT2();              // stage it landed (<=2 groups in flight)
        __syncthreads();         // all warps done reading the slot pre will overwrite

        // prefetch stage it+3 into slot (it+3)&3 == (it-1)&3
        if (pre < niters) {
            const int lb = pre & (STAGES - 1);
            const int k0 = pre * BK;
            const uint32_t ao = a_base + lb * STG_B;
            const uint32_t bo = b_base + lb * STG_B;
            #pragma unroll
            for (int j = 0; j < 2; j++) cp_async16(ao + dst_off[j], a_src[j] + k0);
            #pragma unroll
            for (int j = 0; j < 2; j++) cp_async16(bo + dst_off[j], b_src[j] + k0);
        }
        CP_COMMIT();
        pre++;

        const int buf = it & (STAGES - 1);
        const uint32_t As = a_base + buf * STG_B;
        const uint32_t Bs = b_base + buf * STG_B;

        #pragma unroll
        for (int kk = 0; kk < 2; kk++) {          // two k16 steps per BK=32
            uint32_t af[4][4];
            #pragma unroll
            for (int mt = 0; mt < 4; mt++)
                ldmx4(af[mt], As + a_lm + mt * (16 * ROWB) + kk * 32);
            uint32_t bf[2][4];
            #pragma unroll
            for (int ntp = 0; ntp < 2; ntp++)
                ldmx4(bf[ntp], Bs + b_lm + ntp * (16 * ROWB) + kk * 32);

            #pragma unroll
            for (int mt = 0; mt < 4; mt++) {
                #pragma unroll
                for (int nt = 0; nt < 4; nt++) {
                    const uint32_t* b = bf[nt >> 1];
                    const uint32_t b0 = (nt & 1) ? b[2] : b[0];
                    const uint32_t b1 = (nt & 1) ? b[3] : b[1];
                    mma_f16(acc[mt][nt], af[mt][0], af[mt][1], af[mt][2], af[mt][3], b0, b1);
                }
            }
        }
    }

    // ---- epilogue ----
    #pragma unroll
    for (int mt = 0; mt < 4; mt++) {
        const int r0 = blockIdx.y * TILE_M + warpM * 64 + mt * 16 + lq;
        #pragma unroll
        for (int nt = 0; nt < 4; nt++) {
            const int c0 = blockIdx.x * TILE_N + warpN * 32 + nt * 8 + 2 * lr;
            float v0 = acc[mt][nt][0], v1 = acc[mt][nt][1];
            float v2 = acc[mt][nt][2], v3 = acc[mt][nt][3];
            if (RELU) {
                v0 = fmaxf(v0, 0.0f); v1 = fmaxf(v1, 0.0f);
                v2 = fmaxf(v2, 0.0f); v3 = fmaxf(v3, 0.0f);
            }
            if (OUT_HALF) {
                __half* C = (__half*)Cv + e * sC;
                *reinterpret_cast<__half2*>(C + (long long)r0 * ldc + c0)       = __floats2half2_rn(v0, v1);
                *reinterpret_cast<__half2*>(C + (long long)(r0 + 8) * ldc + c0) = __floats2half2_rn(v2, v3);
            } else {
                float* C = (float*)Cv + e * sC;
                *reinterpret_cast<float2*>(C + (long long)r0 * ldc + c0)       = make_float2(v0, v1);
                *reinterpret_cast<float2*>(C + (long long)(r0 + 8) * ldc + c0) = make_float2(v2, v3);
            }
        }
    }
}

// ---------------- launch ----------------
extern "C" void kernel_launch(void* const* d_in, const int* in_sizes, int n_in,
                              void* d_out, int out_size)
{
    const float* X  = (const float*)d_in[0];
    const float* W1 = (const float*)d_in[2];
    const float* W2 = (const float*)d_in[3];
    float* Y = (float*)d_out;

    __half *Xh, *W1Th, *W2Th, *Hh;
    cudaGetSymbolAddress((void**)&Xh,   g_Xh);
    cudaGetSymbolAddress((void**)&W1Th, g_W1Th);
    cudaGetSymbolAddress((void**)&W2Th, g_W2Th);
    cudaGetSymbolAddress((void**)&Hh,   g_Hh);

    static bool attr_set = false;
    if (!attr_set) {
        cudaFuncSetAttribute(gemm_f16_mma<true, true>,   cudaFuncAttributeMaxDynamicSharedMemorySize, SM_TOTAL);
        cudaFuncSetAttribute(gemm_f16_mma<false, false>, cudaFuncAttributeMaxDynamicSharedMemorySize, SM_TOTAL);
        attr_set = true;
    }

    // 1) X -> fp16
    {
        size_t n4 = (size_t)NE * NC * ND / 4;
        f32_to_f16_kernel<<<(unsigned)((n4 + 255) / 256), 256>>>(X, Xh, n4);
    }
    // 2) W1 [E,D,F] -> W1T [E,F,D] fp16
    {
        dim3 g(NF / 32, ND / 32, NE), b(32, 8);
        transpose_f16_kernel<<<g, b>>>(W1, W1Th, ND, NF);
    }
    // 3) W2 [E,F,D] -> W2T [E,D,F] fp16
    {
        dim3 g(ND / 32, NF / 32, NE), b(32, 8);
        transpose_f16_kernel<<<g, b>>>(W2, W2Th, NF, ND);
    }
    // 4) GEMM1: H = relu(Xh @ W1) fp16 out; M=C, N=F, K=D
    {
        dim3 g(NF / TILE_N, NC / TILE_M, NE);
        gemm_f16_mma<true, true><<<g, 256, SM_TOTAL>>>(
            Xh, W1Th, Hh,
            ND, ND, ND, NF,
            (long long)NC * ND, (long long)NF * ND, (long long)NC * NF);
    }
    // 5) GEMM2: Y = H @ W2 f32 out; M=C, N=D, K=F
    {
        dim3 g(ND / TILE_N, NC / TILE_M, NE);
        gemm_f16_mma<false, false><<<g, 256, SM_TOTAL>>>(
            Hh, W2Th, Y,
            NF, NF, NF, ND,
            (long long)NC * NF, (long long)ND * NF, (long long)NC * ND);
    }
}

// round 6
// speedup vs baseline: 8.3476x; 1.2949x over previous
#include <cuda_runtime.h>
#include <cuda_fp16.h>
#include <cstdint>
#include <cstddef>

#define NE 8
#define NC 4096
#define ND 1024
#define NF 4096

// Device scratch (no allocs allowed)
__device__ __half g_Xh [(size_t)NE * NC * ND];   // X fp16
__device__ __half g_W1h[(size_t)NE * ND * NF];   // W1 fp16 (natural [D,F])
__device__ __half g_W2h[(size_t)NE * NF * ND];   // W2 fp16 (natural [F,D])
__device__ __half g_Hh [(size_t)NE * NC * NF];   // relu(X@W1) fp16

// ---------------- helpers ----------------
__device__ __forceinline__ uint32_t smem_u32(const void* p) {
    uint32_t a;
    asm("{ .reg .u64 t; cvta.to.shared.u64 t, %1; cvt.u32.u64 %0, t; }" : "=r"(a) : "l"(p));
    return a;
}
__device__ __forceinline__ void cp_async16(uint32_t dst, const void* src) {
    asm volatile("cp.async.cg.shared.global [%0], [%1], 16;" :: "r"(dst), "l"(src));
}
#define CP_COMMIT() asm volatile("cp.async.commit_group;" ::: "memory")
#define CP_WAIT2()  asm volatile("cp.async.wait_group 2;" ::: "memory")

__device__ __forceinline__ void ldmx4(uint32_t r[4], uint32_t addr) {
    asm volatile("ldmatrix.sync.aligned.m8n8.x4.shared.b16 {%0,%1,%2,%3}, [%4];"
        : "=r"(r[0]), "=r"(r[1]), "=r"(r[2]), "=r"(r[3]) : "r"(addr));
}
__device__ __forceinline__ void ldmx4t(uint32_t r[4], uint32_t addr) {
    asm volatile("ldmatrix.sync.aligned.m8n8.x4.trans.shared.b16 {%0,%1,%2,%3}, [%4];"
        : "=r"(r[0]), "=r"(r[1]), "=r"(r[2]), "=r"(r[3]) : "r"(addr));
}
__device__ __forceinline__ void mma_f16(float d[4],
                                        uint32_t a0, uint32_t a1, uint32_t a2, uint32_t a3,
                                        uint32_t b0, uint32_t b1) {
    asm volatile("mma.sync.aligned.m16n8k16.row.col.f32.f16.f16.f32 "
        "{%0,%1,%2,%3}, {%4,%5,%6,%7}, {%8,%9}, {%0,%1,%2,%3};"
        : "+f"(d[0]), "+f"(d[1]), "+f"(d[2]), "+f"(d[3])
        : "r"(a0), "r"(a1), "r"(a2), "r"(a3), "r"(b0), "r"(b1));
}

// ---------------- prep: f32 -> f16 cast ----------------
__global__ void f32_to_f16_kernel(const float* __restrict__ in, __half* __restrict__ out, size_t n4) {
    size_t i = (size_t)blockIdx.x * blockDim.x + threadIdx.x;
    if (i >= n4) return;
    float4 v = reinterpret_cast<const float4*>(in)[i];
    __half2 h0 = __floats2half2_rn(v.x, v.y);
    __half2 h1 = __floats2half2_rn(v.z, v.w);
    uint2 o;
    o.x = *reinterpret_cast<uint32_t*>(&h0);
    o.y = *reinterpret_cast<uint32_t*>(&h1);
    reinterpret_cast<uint2*>(out)[i] = o;
}

// ---------------- fp16 mma.sync GEMM ----------------
// C[M,N] = A[M,K] (K-major) * B[K,N] (N-major, natural weight layout).
// CTA 128x128, BK=32, 4-stage cp.async, 2 CTAs/SM, fragment double-buffering.
// 8 warps: warpM = wid&1, warpN = wid>>1; warp tile 64x32.
#define STAGES 4
#define BK 32
#define TILE_M 128
#define TILE_N 128
#define AROWB 80                     // A smem: 64B data + 16 pad per row (128 rows)
#define BROWB 272                    // B smem: 256B data + 16 pad per k-row (32 rows)
#define STG_A (TILE_M * AROWB)       // 10240 B
#define STG_B (BK * BROWB)           // 8704 B
#define SM_TOTAL (STAGES * (STG_A + STG_B))   // 75776 B -> 2 CTAs/SM

template<bool RELU, bool OUT_HALF>
__global__ __launch_bounds__(256, 2)
void gemm_f16_mma(const __half* __restrict__ A, const __half* __restrict__ B,
                  void* __restrict__ Cv,
                  int K, int lda, int ldb, int ldc,
                  long long sA, long long sB, long long sC)
{
    extern __shared__ char smem[];
    const uint32_t a_base = smem_u32(smem);
    const uint32_t b_base = a_base + STAGES * STG_A;

    const int tid = threadIdx.x;
    const int wid = tid >> 5;
    const int lane = tid & 31;
    const int lq = lane >> 2;
    const int lr = lane & 3;
    const int warpM = wid & 1;
    const int warpN = wid >> 1;

    const long long e = blockIdx.z;
    const __half* Ag = A + e * sA + (long long)blockIdx.y * TILE_M * lda;
    const __half* Bg = B + e * sB + (long long)blockIdx.x * TILE_N;   // B: [K,N] rows

    // cp.async slots (512 chunks of 16B per matrix per stage; 2 per thread each)
    // A chunk g: row=g>>2 (0..127), seg=g&3 ; B chunk g: row=g>>4 (0..31), c=g&15
    uint32_t a_dst[2], b_dst[2], a_off[2], b_off[2];
    #pragma unroll
    for (int j = 0; j < 2; j++) {
        int g = tid + 256 * j;
        int ar = g >> 2, as = g & 3;
        a_dst[j] = ar * AROWB + as * 16;
        a_off[j] = (uint32_t)(ar * lda + as * 8);       // halfs; +k0 per stage
        int br = g >> 4, bc = g & 15;
        b_dst[j] = br * BROWB + bc * 16;
        b_off[j] = (uint32_t)(br * ldb + bc * 8);       // halfs; +k0*ldb per stage
    }

    // ldmatrix source offsets
    // A (non-trans): rows m, 16B phase select — unchanged from validated R5 layout
    const uint32_t a_lm = (uint32_t)(warpM * 64 + (lane & 15)) * AROWB + ((lane >> 4) & 1) * 16;
    // B (trans): row = kk*16 + (lane&15); col = warpN*32 + ntp*16 + ((lane>>4)&1)*8
    const uint32_t b_lm = (uint32_t)(lane & 15) * BROWB
                        + (uint32_t)(warpN * 32 + ((lane >> 4) & 1) * 8) * 2;

    const int niters = K / BK;

    // prologue: stages 0..2
    #pragma unroll
    for (int s = 0; s < STAGES - 1; s++) {
        const uint32_t ao = a_base + s * STG_A;
        const uint32_t bo = b_base + s * STG_B;
        const uint32_t ka = (uint32_t)(s * BK);
        const uint32_t kb = (uint32_t)(s * BK) * (uint32_t)ldb;
        #pragma unroll
        for (int j = 0; j < 2; j++) cp_async16(ao + a_dst[j], Ag + a_off[j] + ka);
        #pragma unroll
        for (int j = 0; j < 2; j++) cp_async16(bo + b_dst[j], Bg + b_off[j] + kb);
        CP_COMMIT();
    }

    float acc[4][4][4];
    #pragma unroll
    for (int i = 0; i < 4; i++)
        #pragma unroll
        for (int j = 0; j < 4; j++)
            #pragma unroll
            for (int k = 0; k < 4; k++)
                acc[i][j][k] = 0.0f;

    uint32_t afc[4][4], bfc[2][4];   // kk=0 frags
    uint32_t afn[4][4], bfn[2][4];   // kk=1 frags

    // wait stage 0, load kk=0 frags
    CP_WAIT2();
    __syncthreads();
    #pragma unroll
    for (int mt = 0; mt < 4; mt++) ldmx4(afc[mt], a_base + a_lm + mt * (16 * AROWB));
    #pragma unroll
    for (int np = 0; np < 2; np++) ldmx4t(bfc[np], b_base + b_lm + np * 32);

    int pre = STAGES - 1;

    for (int it = 0; it < niters; it++) {
        const int buf = it & (STAGES - 1);
        const uint32_t As = a_base + buf * STG_A;
        const uint32_t Bs = b_base + buf * STG_B;

        // ---- phase kk=0: load kk=1 frags, prefetch gmem, MMA on cur ----
        #pragma unroll
        for (int mt = 0; mt < 4; mt++) ldmx4(afn[mt], As + a_lm + mt * (16 * AROWB) + 32);
        #pragma unroll
        for (int np = 0; np < 2; np++) ldmx4t(bfn[np], Bs + b_lm + 16 * BROWB + np * 32);

        if (pre < niters) {
            const int lb = pre & (STAGES - 1);
            const uint32_t ao = a_base + lb * STG_A;
            const uint32_t bo = b_base + lb * STG_B;
            const uint32_t ka = (uint32_t)(pre * BK);
            const uint32_t kb = ka * (uint32_t)ldb;
            #pragma unroll
            for (int j = 0; j < 2; j++) cp_async16(ao + a_dst[j], Ag + a_off[j] + ka);
            #pragma unroll
            for (int j = 0; j < 2; j++) cp_async16(bo + b_dst[j], Bg + b_off[j] + kb);
        }
        CP_COMMIT();
        pre++;

        #pragma unroll
        for (int mt = 0; mt < 4; mt++)
            #pragma unroll
            for (int nt = 0; nt < 4; nt++) {
                const uint32_t* b = bfc[nt >> 1];
                mma_f16(acc[mt][nt], afc[mt][0], afc[mt][1], afc[mt][2], afc[mt][3],
                        (nt & 1) ? b[2] : b[0], (nt & 1) ? b[3] : b[1]);
            }

        // ---- phase kk=1: advance smem stage, load next kk=0 frags, MMA on nxt ----
        if (it + 1 < niters) {
            CP_WAIT2();          // stage it+1 landed
            __syncthreads();     // all reads of the slot the next prefetch overwrites are issued
            const int nb = (it + 1) & (STAGES - 1);
            const uint32_t As2 = a_base + nb * STG_A;
            const uint32_t Bs2 = b_base + nb * STG_B;
            #pragma unroll
            for (int mt = 0; mt < 4; mt++) ldmx4(afc[mt], As2 + a_lm + mt * (16 * AROWB));
            #pragma unroll
            for (int np = 0; np < 2; np++) ldmx4t(bfc[np], Bs2 + b_lm + np * 32);
        }

        #pragma unroll
        for (int mt = 0; mt < 4; mt++)
            #pragma unroll
            for (int nt = 0; nt < 4; nt++) {
                const uint32_t* b = bfn[nt >> 1];
                mma_f16(acc[mt][nt], afn[mt][0], afn[mt][1], afn[mt][2], afn[mt][3],
                        (nt & 1) ? b[2] : b[0], (nt & 1) ? b[3] : b[1]);
            }
    }

    // ---- epilogue ----
    #pragma unroll
    for (int mt = 0; mt < 4; mt++) {
        const int r0 = blockIdx.y * TILE_M + warpM * 64 + mt * 16 + lq;
        #pragma unroll
        for (int nt = 0; nt < 4; nt++) {
            const int c0 = blockIdx.x * TILE_N + warpN * 32 + nt * 8 + 2 * lr;
            float v0 = acc[mt][nt][0], v1 = acc[mt][nt][1];
            float v2 = acc[mt][nt][2], v3 = acc[mt][nt][3];
            if (RELU) {
                v0 = fmaxf(v0, 0.0f); v1 = fmaxf(v1, 0.0f);
                v2 = fmaxf(v2, 0.0f); v3 = fmaxf(v3, 0.0f);
            }
            if (OUT_HALF) {
                __half* C = (__half*)Cv + e * sC;
                *reinterpret_cast<__half2*>(C + (long long)r0 * ldc + c0)       = __floats2half2_rn(v0, v1);
                *reinterpret_cast<__half2*>(C + (long long)(r0 + 8) * ldc + c0) = __floats2half2_rn(v2, v3);
            } else {
                float* C = (float*)Cv + e * sC;
                *reinterpret_cast<float2*>(C + (long long)r0 * ldc + c0)       = make_float2(v0, v1);
                *reinterpret_cast<float2*>(C + (long long)(r0 + 8) * ldc + c0) = make_float2(v2, v3);
            }
        }
    }
}

// ---------------- launch ----------------
extern "C" void kernel_launch(void* const* d_in, const int* in_sizes, int n_in,
                              void* d_out, int out_size)
{
    const float* X  = (const float*)d_in[0];
    const float* W1 = (const float*)d_in[2];
    const float* W2 = (const float*)d_in[3];
    float* Y = (float*)d_out;

    __half *Xh, *W1h, *W2h, *Hh;
    cudaGetSymbolAddress((void**)&Xh,  g_Xh);
    cudaGetSymbolAddress((void**)&W1h, g_W1h);
    cudaGetSymbolAddress((void**)&W2h, g_W2h);
    cudaGetSymbolAddress((void**)&Hh,  g_Hh);

    static bool attr_set = false;
    if (!attr_set) {
        cudaFuncSetAttribute(gemm_f16_mma<true, true>,   cudaFuncAttributeMaxDynamicSharedMemorySize, SM_TOTAL);
        cudaFuncSetAttribute(gemm_f16_mma<false, false>, cudaFuncAttributeMaxDynamicSharedMemorySize, SM_TOTAL);
        attr_set = true;
    }

    // casts (no transposes needed anymore)
    {
        size_t n4 = (size_t)NE * NC * ND / 4;
        f32_to_f16_kernel<<<(unsigned)((n4 + 255) / 256), 256>>>(X, Xh, n4);
    }
    {
        size_t n4 = (size_t)NE * ND * NF / 4;
        f32_to_f16_kernel<<<(unsigned)((n4 + 255) / 256), 256>>>(W1, W1h, n4);
    }
    {
        size_t n4 = (size_t)NE * NF * ND / 4;
        f32_to_f16_kernel<<<(unsigned)((n4 + 255) / 256), 256>>>(W2, W2h, n4);
    }

    // GEMM1: H = relu(Xh @ W1h); M=C, N=F, K=D; B rows stride ldb=NF
    {
        dim3 g(NF / TILE_N, NC / TILE_M, NE);
        gemm_f16_mma<true, true><<<g, 256, SM_TOTAL>>>(
            Xh, W1h, Hh,
            ND, ND, NF, NF,
            (long long)NC * ND, (long long)ND * NF, (long long)NC * NF);
    }
    // GEMM2: Y = H @ W2h; M=C, N=D, K=F; ldb=ND
    {
        dim3 g(ND / TILE_N, NC / TILE_M, NE);
        gemm_f16_mma<false, false><<<g, 256, SM_TOTAL>>>(
            Hh, W2h, Y,
            NF, NF, ND, ND,
            (long long)NC * NF, (long long)NF * ND, (long long)NC * ND);
    }
}